// round 14
// baseline (speedup 1.0000x reference)
#include <cuda_runtime.h>
#include <math.h>

// Problem constants
#define NROWS 2048
#define NN    2048
#define DIN   256
#define H     32
#define DOUT  256

#define NSPLIT 4
#define CHUNK  (NN / NSPLIT)     // 512 neighbors per split
#define BM 32                    // rows per flash block
#define BN 32                    // neighbor tile
#define NBS (DIN + 8)            // nb smem stride (conflict-free PV B frags)
#define NAS 40                   // naT stride (banks 8t+g, conflict-free S B frags)
#define FCKS 4                   // fc K-split factor (K=128 each)

// Scratch (device globals: no allocation allowed)
__device__ float g_xatt[NROWS * H];              // tf32 bits
__device__ float g_natt[NN * H];                 // tf32 bits
__device__ float g_ntf[NN * DIN];                // neibs pre-converted to tf32 (2 MB)
__device__ float g_agg[NROWS * DIN];
__device__ float g_pacc[NSPLIT * NROWS * DIN];   // 8 MB partial accumulators
__device__ float g_pl[NSPLIT * NROWS];
__device__ float g_fcp[FCKS * NROWS * DOUT];     // fc K-split partials (8 MB)

// ---- tf32 mma helpers -----------------------------------------------------
__device__ __forceinline__ unsigned f2t(float f) {
    unsigned r;
    asm("cvt.rn.tf32.f32 %0, %1;" : "=r"(r) : "f"(f));
    return r;
}
__device__ __forceinline__ void mma8(float4& d,
                                     unsigned a0, unsigned a1,
                                     unsigned a2, unsigned a3,
                                     unsigned b0, unsigned b1) {
    asm("mma.sync.aligned.m16n8k8.row.col.f32.tf32.tf32.f32 "
        "{%0,%1,%2,%3}, {%4,%5,%6,%7}, {%8,%9}, {%0,%1,%2,%3};"
        : "+f"(d.x), "+f"(d.y), "+f"(d.z), "+f"(d.w)
        : "r"(a0), "r"(a1), "r"(a2), "r"(a3), "r"(b0), "r"(b1));
}
__device__ __forceinline__ unsigned fu(float f) { return __float_as_uint(f); }

// ---- packed f32x2 helpers (fc kernel) -------------------------------------
__device__ __forceinline__ void fma2(unsigned long long& d,
                                     unsigned long long a,
                                     unsigned long long b) {
    asm("fma.rn.f32x2 %0, %1, %2, %0;" : "+l"(d) : "l"(a), "l"(b));
}
__device__ __forceinline__ unsigned long long bcast2(float v) {
    unsigned long long r;
    asm("mov.b64 %0, {%1, %1};" : "=l"(r) : "r"(__float_as_uint(v)));
    return r;
}
__device__ __forceinline__ float2 unpack2(unsigned long long v) {
    float2 f;
    unsigned lo, hi;
    asm("mov.b64 {%0, %1}, %2;" : "=r"(lo), "=r"(hi) : "l"(v));
    f.x = __uint_as_float(lo); f.y = __uint_as_float(hi);
    return f;
}

// ---------------------------------------------------------------------------
// Kernel 0: pre-convert neibs to tf32 bits (one float4 per thread).
// Grid = 512 x 256.
// ---------------------------------------------------------------------------
__global__ __launch_bounds__(256) void cvt_neibs_kernel(
        const float* __restrict__ neibs) {
    const int i4 = blockIdx.x * 256 + threadIdx.x;
    float4 v = *(const float4*)(neibs + (size_t)i4 * 4);
    float4 o;
    o.x = __uint_as_float(f2t(v.x));
    o.y = __uint_as_float(f2t(v.y));
    o.z = __uint_as_float(f2t(v.z));
    o.w = __uint_as_float(f2t(v.w));
    *(float4*)(g_ntf + (size_t)i4 * 4) = o;
}

// ---------------------------------------------------------------------------
// Kernel 1: both attention MLPs in one launch (grid = 512).
// Outputs are stored as tf32 bits (consumed only by MMA in flash).
// ---------------------------------------------------------------------------
__global__ __launch_bounds__(256) void att_mlp_kernel(
        const float* __restrict__ x, const float* __restrict__ neibs,
        const float* __restrict__ xw1, const float* __restrict__ xb1,
        const float* __restrict__ xw2, const float* __restrict__ xb2,
        const float* __restrict__ nw1, const float* __restrict__ nb1,
        const float* __restrict__ nw2, const float* __restrict__ nb2) {
    __shared__ float w1s[DIN * H];
    __shared__ float w2s[H * H];
    __shared__ float b1s[H], b2s[H];
    __shared__ float xs[8 * DIN];
    __shared__ float t1s[8 * 33];

    const int tid = threadIdx.x;
    const int which = blockIdx.x >= 256;
    const int row0 = (blockIdx.x & 255) * 8;

    const float* in = which ? neibs : x;
    const float* w1 = which ? nw1 : xw1;
    const float* b1 = which ? nb1 : xb1;
    const float* w2 = which ? nw2 : xw2;
    const float* b2 = which ? nb2 : xb2;

    for (int i = tid; i < DIN * H; i += 256) w1s[i] = w1[i];
    for (int i = tid; i < H * H; i += 256)   w2s[i] = w2[i];
    if (tid < H) { b1s[tid] = b1[tid]; b2s[tid] = b2[tid]; }
    for (int i = tid; i < 8 * DIN; i += 256) xs[i] = in[row0 * DIN + i];
    __syncthreads();

    const int r = tid >> 5;
    const int h = tid & 31;

    float a0 = b1s[h], a1 = 0.f, a2 = 0.f, a3 = 0.f;
    #pragma unroll 8
    for (int k = 0; k < DIN; k += 4) {
        a0 += xs[r * DIN + k + 0] * w1s[(k + 0) * H + h];
        a1 += xs[r * DIN + k + 1] * w1s[(k + 1) * H + h];
        a2 += xs[r * DIN + k + 2] * w1s[(k + 2) * H + h];
        a3 += xs[r * DIN + k + 3] * w1s[(k + 3) * H + h];
    }
    float acc = (a0 + a1) + (a2 + a3);

    t1s[r * 33 + h] = tanhf(acc);
    __syncwarp();

    float c0 = b2s[h], c1 = 0.f, c2 = 0.f, c3 = 0.f;
    #pragma unroll
    for (int kk = 0; kk < H; kk += 4) {
        c0 += t1s[r * 33 + kk + 0] * w2s[(kk + 0) * H + h];
        c1 += t1s[r * 33 + kk + 1] * w2s[(kk + 1) * H + h];
        c2 += t1s[r * 33 + kk + 2] * w2s[(kk + 2) * H + h];
        c3 += t1s[r * 33 + kk + 3] * w2s[(kk + 3) * H + h];
    }
    float acc2 = (c0 + c1) + (c2 + c3);

    float* out = which ? g_natt : g_xatt;
    out[(row0 + r) * H + h] = __uint_as_float(f2t(acc2));   // tf32 bits
}

// ---------------------------------------------------------------------------
// Kernel 2: split-K flash aggregation. BOTH matmuls via tf32 MMA.
// All staged operands are pre-converted tf32 bits -> staging is pure copy.
// Grid = 64 row-blocks * 4 splits = 256 blocks, 256 threads (8 warps).
// ---------------------------------------------------------------------------
__global__ __launch_bounds__(256) void flash_part_kernel(
        const float* __restrict__ mask) {
    __shared__ float xa[BM * 36];       // x_att tile (tf32 bits), block-invariant
    __shared__ float naT[H * NAS];      // transposed neib_att tile (tf32 bits)
    __shared__ float ps[BM * 36];       // exp weights (tf32 bits)
    __shared__ float nb[BN * NBS];      // neighbor features (tf32 bits) 33 KB
    __shared__ float lred[4][BM];       // l reduction across n-quarter warps

    const int tid   = threadIdx.x;
    const int split = blockIdx.x & (NSPLIT - 1);
    const int row0  = (blockIdx.x >> 2) * BM;
    const int jstart = split * CHUNK;

    const int warp = tid >> 5;
    const int lane = tid & 31;
    const int gid  = lane >> 2;         // 0..7
    const int tg   = lane & 3;          // 0..3
    const int n0   = warp * 32;         // PV n-slice

    // S-phase warp mapping: mhalf (rows mh*16..+15), nquarter (cols nq*8..+7)
    const int mh = warp >> 2;           // 0..1
    const int nq = warp & 3;            // 0..3
    const int srowA = mh * 16 + gid;    // fragment row A
    const int srowB = srowA + 8;        // fragment row B
    const int scol  = nq * 8 + 2 * tg;  // fragment col pair base

    // stage xa once (already tf32 bits)
    for (int i = tid; i < BM * H; i += 256) {
        int r = i >> 5, hh = i & 31;
        xa[r * 36 + hh] = g_xatt[(size_t)(row0 + r) * H + hh];
    }
    __syncthreads();

    // preload S A-fragments (x_att rows for this warp's m-half), 16 regs
    unsigned sa[4][4];
    #pragma unroll
    for (int kt = 0; kt < 4; kt++) {
        const int kc = kt * 8 + tg;
        sa[kt][0] = fu(xa[srowA * 36 + kc]);
        sa[kt][1] = fu(xa[srowB * 36 + kc]);
        sa[kt][2] = fu(xa[srowA * 36 + kc + 4]);
        sa[kt][3] = fu(xa[srowB * 36 + kc + 4]);
    }

    float lacc0 = 0.0f, lacc1 = 0.0f;   // l partials for rows srowA, srowB
    float4 acc[2][4];                   // PV accum [m-tile][n-tile]
    #pragma unroll
    for (int mt = 0; mt < 2; mt++)
        #pragma unroll
        for (int nt = 0; nt < 4; nt++)
            acc[mt][nt] = make_float4(0.f, 0.f, 0.f, 0.f);

    for (int t = 0; t < CHUNK / BN; t++) {
        const int jcol0 = jstart + t * BN;

        // prefetch mask in fragment layout (overlaps staging)
        float2 mv0 = *(const float2*)(mask + (size_t)(row0 + srowA) * NN + jcol0 + scol);
        float2 mv1 = *(const float2*)(mask + (size_t)(row0 + srowB) * NN + jcol0 + scol);

        // stage neib_att tile transposed (tf32 bits, pure copy)
        for (int i = tid; i < BN * H; i += 256) {
            int j = i & 31, hh = i >> 5;
            naT[hh * NAS + j] = g_natt[(size_t)(jcol0 + j) * H + hh];
        }
        // stage neighbor features (tf32 bits, pure float4 copy)
        #pragma unroll
        for (int i = tid; i < BN * DIN / 4; i += 256) {
            int j = i >> 6, c4 = (i & 63) * 4;
            *(float4*)(nb + j * NBS + c4) =
                *(const float4*)(g_ntf + (size_t)(jcol0 + j) * DIN + c4);
        }
        __syncthreads();

        // ---- S = x_att @ naT^T via MMA (K=32 in 4 k-steps) ----
        float4 sfrag = make_float4(0.f, 0.f, 0.f, 0.f);
        #pragma unroll
        for (int kt = 0; kt < 4; kt++) {
            // B frags: banks 8t+g, conflict-free at stride NAS=40
            unsigned b0 = fu(naT[(kt * 8 + tg) * NAS + nq * 8 + gid]);
            unsigned b1 = fu(naT[(kt * 8 + tg + 4) * NAS + nq * 8 + gid]);
            mma8(sfrag, sa[kt][0], sa[kt][1], sa[kt][2], sa[kt][3], b0, b1);
        }

        // mask -> exp -> p (exp(0)=1 on masked entries matches reference)
        float p00 = __expf(sfrag.x * mv0.x);
        float p01 = __expf(sfrag.y * mv0.y);
        float p10 = __expf(sfrag.z * mv1.x);
        float p11 = __expf(sfrag.w * mv1.y);
        lacc0 += p00 + p01;
        lacc1 += p10 + p11;

        *(float2*)(ps + srowA * 36 + scol) = make_float2(
            __uint_as_float(f2t(p00)), __uint_as_float(f2t(p01)));
        *(float2*)(ps + srowB * 36 + scol) = make_float2(
            __uint_as_float(f2t(p10)), __uint_as_float(f2t(p11)));

        __syncthreads();   // ps visible to all warps (PV A-frags span 32 rows)

        // ---- PV: tf32 mma, K = 32 in 4 steps (conflict-free scalar frags) --
        #pragma unroll
        for (int kt = 0; kt < 4; kt++) {
            const int kc = kt * 8 + tg;
            unsigned a0m0 = fu(ps[gid * 36 + kc]);
            unsigned a1m0 = fu(ps[(gid + 8) * 36 + kc]);
            unsigned a2m0 = fu(ps[gid * 36 + kc + 4]);
            unsigned a3m0 = fu(ps[(gid + 8) * 36 + kc + 4]);
            unsigned a0m1 = fu(ps[(gid + 16) * 36 + kc]);
            unsigned a1m1 = fu(ps[(gid + 24) * 36 + kc]);
            unsigned a2m1 = fu(ps[(gid + 16) * 36 + kc + 4]);
            unsigned a3m1 = fu(ps[(gid + 24) * 36 + kc + 4]);
            #pragma unroll
            for (int nt = 0; nt < 4; nt++) {
                const int nc = n0 + nt * 8 + gid;
                unsigned b0 = fu(nb[(kt * 8 + tg) * NBS + nc]);
                unsigned b1 = fu(nb[(kt * 8 + tg + 4) * NBS + nc]);
                mma8(acc[0][nt], a0m0, a1m0, a2m0, a3m0, b0, b1);
                mma8(acc[1][nt], a0m1, a1m1, a2m1, a3m1, b0, b1);
            }
        }
        __syncthreads();
    }

    // ---- l reduction: over tg lanes, then across the 4 n-quarter warps ----
    lacc0 += __shfl_xor_sync(0xffffffffu, lacc0, 1);
    lacc0 += __shfl_xor_sync(0xffffffffu, lacc0, 2);
    lacc1 += __shfl_xor_sync(0xffffffffu, lacc1, 1);
    lacc1 += __shfl_xor_sync(0xffffffffu, lacc1, 2);
    if (tg == 0) {
        lred[nq][srowA] = lacc0;
        lred[nq][srowB] = lacc1;
    }
    __syncthreads();
    if (tid < BM) {
        float L = lred[0][tid] + lred[1][tid] + lred[2][tid] + lred[3][tid];
        g_pl[split * NROWS + row0 + tid] = L;
    }

    // partial outputs (fragment layout -> g_pacc)
    #pragma unroll
    for (int mt = 0; mt < 2; mt++) {
        const int r1 = gid + mt * 16;
        const int r2 = gid + 8 + mt * 16;
        const size_t b1 = ((size_t)split * NROWS + row0 + r1) * DIN;
        const size_t b2 = ((size_t)split * NROWS + row0 + r2) * DIN;
        #pragma unroll
        for (int nt = 0; nt < 4; nt++) {
            const int c = n0 + nt * 8 + 2 * tg;
            *(float2*)(g_pacc + b1 + c) = make_float2(acc[mt][nt].x, acc[mt][nt].y);
            *(float2*)(g_pacc + b2 + c) = make_float2(acc[mt][nt].z, acc[mt][nt].w);
        }
    }
}

// ---------------------------------------------------------------------------
// Kernel 3: combine split partials -> agg = sigmoid((Σ pacc) / (Σ l))
// ---------------------------------------------------------------------------
__global__ __launch_bounds__(256) void combine_kernel() {
    const int tid  = threadIdx.x;
    const int row  = blockIdx.x * 8 + (tid >> 5);
    const int lane = tid & 31;

    float L = 0.0f;
    #pragma unroll
    for (int s = 0; s < NSPLIT; s++)
        L += g_pl[s * NROWS + row];
    const float invL = 1.0f / L;

    #pragma unroll
    for (int half = 0; half < 2; half++) {
        const int c = half * 128 + lane * 4;
        float4 a = make_float4(0.f, 0.f, 0.f, 0.f);
        #pragma unroll
        for (int s = 0; s < NSPLIT; s++) {
            float4 v = *(const float4*)(g_pacc + ((size_t)s * NROWS + row) * DIN + c);
            a.x += v.x; a.y += v.y; a.z += v.z; a.w += v.w;
        }
        float4 o;
        o.x = 1.0f / (1.0f + __expf(-a.x * invL));
        o.y = 1.0f / (1.0f + __expf(-a.y * invL));
        o.z = 1.0f / (1.0f + __expf(-a.z * invL));
        o.w = 1.0f / (1.0f + __expf(-a.w * invL));
        *(float4*)(g_agg + (size_t)row * DIN + c) = o;
    }
}

// ---------------------------------------------------------------------------
// Kernel 4a: fc partial GEMM, f32x2, K split in 4 (128 each).
// Grid = 64 rowblocks * 4 colblocks * 4 ksplit = 1024 blocks, 128 threads.
// ---------------------------------------------------------------------------
__global__ __launch_bounds__(128) void fc_part_kernel(
        const float* __restrict__ x, const float* __restrict__ fcw) {
    __shared__ float AtT[32 * 36];     // [k][row], padded
    __shared__ float Wt[32 * 64];

    const int b    = blockIdx.x;
    const int ks   = b & 3;
    const int col0 = ((b >> 2) & 3) * 64;
    const int row0 = (b >> 4) * 32;

    const float* A = (ks < 2) ? x : g_agg;                // [2048, 256]
    const int acol0 = (ks & 1) * 128;                     // A column base
    const float* W = fcw + (size_t)ks * 128 * DOUT;       // 128 K-rows

    const int tid = threadIdx.x;
    const int rg  = tid >> 4;          // 0..7 -> rows rg*4..+3
    const int cq  = tid & 15;          // 0..15 -> cols cq*4..+3

    unsigned long long acc[4][2];
    #pragma unroll
    for (int i = 0; i < 4; i++) { acc[i][0] = 0ULL; acc[i][1] = 0ULL; }

    #pragma unroll
    for (int kt = 0; kt < 4; kt++) {
        const int kbase = kt * 32;
        // stage A transposed
        for (int i = tid; i < 32 * 32; i += 128) {
            int r = i >> 5, kk = i & 31;
            AtT[kk * 36 + r] = A[(size_t)(row0 + r) * DIN + acol0 + kbase + kk];
        }
        // stage W tile
        #pragma unroll
        for (int i = tid; i < 32 * 64 / 4; i += 128) {
            int kk = i >> 4, cc = (i & 15) * 4;
            *(float4*)(Wt + kk * 64 + cc) =
                *(const float4*)(W + (size_t)(kbase + kk) * DOUT + col0 + cc);
        }
        __syncthreads();

        #pragma unroll 8
        for (int k = 0; k < 32; k++) {
            float4 av = *(const float4*)(AtT + k * 36 + rg * 4);
            ulonglong2 wv = *(const ulonglong2*)(Wt + k * 64 + cq * 4);
            unsigned long long a0 = bcast2(av.x);
            unsigned long long a1 = bcast2(av.y);
            unsigned long long a2 = bcast2(av.z);
            unsigned long long a3 = bcast2(av.w);
            fma2(acc[0][0], a0, wv.x); fma2(acc[0][1], a0, wv.y);
            fma2(acc[1][0], a1, wv.x); fma2(acc[1][1], a1, wv.y);
            fma2(acc[2][0], a2, wv.x); fma2(acc[2][1], a2, wv.y);
            fma2(acc[3][0], a3, wv.x); fma2(acc[3][1], a3, wv.y);
        }
        __syncthreads();
    }

    #pragma unroll
    for (int i = 0; i < 4; i++) {
        float2 lo = unpack2(acc[i][0]);
        float2 hi = unpack2(acc[i][1]);
        *(float4*)(g_fcp + ((size_t)ks * NROWS + row0 + rg * 4 + i) * DOUT
                   + col0 + cq * 4) = make_float4(lo.x, lo.y, hi.x, hi.y);
    }
}

// ---------------------------------------------------------------------------
// Kernel 4b: out = sigmoid(sum of 4 partials + b)
// ---------------------------------------------------------------------------
__global__ __launch_bounds__(256) void fc_epilogue_kernel(
        const float* __restrict__ fcb, float* __restrict__ out) {
    const int idx4 = blockIdx.x * 256 + threadIdx.x;
    const int off  = idx4 * 4;
    const int col  = off & (DOUT - 1);

    float4 a = *(const float4*)(g_fcp + off);
    #pragma unroll
    for (int s = 1; s < FCKS; s++) {
        float4 p = *(const float4*)(g_fcp + (size_t)s * NROWS * DOUT + off);
        a.x += p.x; a.y += p.y; a.z += p.z; a.w += p.w;
    }
    float4 b4 = *(const float4*)(fcb + col);
    float4 o;
    o.x = 1.0f / (1.0f + __expf(-(a.x + b4.x)));
    o.y = 1.0f / (1.0f + __expf(-(a.y + b4.y)));
    o.z = 1.0f / (1.0f + __expf(-(a.z + b4.z)));
    o.w = 1.0f / (1.0f + __expf(-(a.w + b4.w)));
    *(float4*)(out + off) = o;
}

// ---------------------------------------------------------------------------
extern "C" void kernel_launch(void* const* d_in, const int* in_sizes, int n_in,
                              void* d_out, int out_size) {
    (void)in_sizes; (void)n_in; (void)out_size;
    const float* x      = (const float*)d_in[0];
    const float* neibs  = (const float*)d_in[1];
    // d_in[2] = edge_emb: dead code in the reference, intentionally untouched
    const float* mask   = (const float*)d_in[3];
    const float* ax_w1  = (const float*)d_in[4];
    const float* ax_b1  = (const float*)d_in[5];
    const float* ax_w2  = (const float*)d_in[6];
    const float* ax_b2  = (const float*)d_in[7];
    const float* an_w1  = (const float*)d_in[8];
    const float* an_b1  = (const float*)d_in[9];
    const float* an_w2  = (const float*)d_in[10];
    const float* an_b2  = (const float*)d_in[11];
    // d_in[12..15] = ae_* : dead code
    const float* fcx_w  = (const float*)d_in[16];
    const float* fcx_b  = (const float*)d_in[17];
    float* out = (float*)d_out;

    cvt_neibs_kernel<<<NN * DIN / 1024, 256>>>(neibs);
    att_mlp_kernel<<<512, 256>>>(x, neibs, ax_w1, ax_b1, ax_w2, ax_b2,
                                 an_w1, an_b1, an_w2, an_b2);
    flash_part_kernel<<<(NROWS / BM) * NSPLIT, 256>>>(mask);
    combine_kernel<<<NROWS / 8, 256>>>();
    fc_part_kernel<<<(NROWS / 32) * (DOUT / 64) * FCKS, 128>>>(x, fcx_w);
    fc_epilogue_kernel<<<NROWS * DOUT / 1024, 256>>>(fcx_b, out);
}

// round 17
// speedup vs baseline: 1.0684x; 1.0684x over previous
#include <cuda_runtime.h>
#include <math.h>

// Problem constants
#define NROWS 2048
#define NN    2048
#define DIN   256
#define H     32
#define DOUT  256

#define NSPLIT 4
#define CHUNK  (NN / NSPLIT)     // 512 neighbors per split
#define BM 32                    // rows per flash block
#define BN 32                    // neighbor tile
#define NBS (DIN + 8)            // nb smem stride (conflict-free PV B frags)
#define NAS 40                   // naT stride (banks 8t+g, conflict-free S B frags)
#define FCKS 8                   // fc K-split factor (K=64 each)

// Scratch (device globals: no allocation allowed)
__device__ float g_xatt[NROWS * H];
__device__ float g_natt[NN * H];
__device__ float g_agg[NROWS * DIN];
__device__ float g_pacc[NSPLIT * NROWS * DIN];   // 8 MB partial accumulators
__device__ float g_pl[NSPLIT * NROWS];
__device__ float g_fcp[FCKS * NROWS * DOUT];     // fc K-split partials (16 MB)

// ---- tf32 mma helpers -----------------------------------------------------
__device__ __forceinline__ unsigned f2t(float f) {
    unsigned r;
    asm("cvt.rn.tf32.f32 %0, %1;" : "=r"(r) : "f"(f));
    return r;
}
__device__ __forceinline__ void mma8(float4& d,
                                     unsigned a0, unsigned a1,
                                     unsigned a2, unsigned a3,
                                     unsigned b0, unsigned b1) {
    asm("mma.sync.aligned.m16n8k8.row.col.f32.tf32.tf32.f32 "
        "{%0,%1,%2,%3}, {%4,%5,%6,%7}, {%8,%9}, {%0,%1,%2,%3};"
        : "+f"(d.x), "+f"(d.y), "+f"(d.z), "+f"(d.w)
        : "r"(a0), "r"(a1), "r"(a2), "r"(a3), "r"(b0), "r"(b1));
}
__device__ __forceinline__ unsigned fu(float f) { return __float_as_uint(f); }

// ---- packed f32x2 helpers (fc kernel) -------------------------------------
__device__ __forceinline__ void fma2(unsigned long long& d,
                                     unsigned long long a,
                                     unsigned long long b) {
    asm("fma.rn.f32x2 %0, %1, %2, %0;" : "+l"(d) : "l"(a), "l"(b));
}
__device__ __forceinline__ unsigned long long bcast2(float v) {
    unsigned long long r;
    asm("mov.b64 %0, {%1, %1};" : "=l"(r) : "r"(__float_as_uint(v)));
    return r;
}
__device__ __forceinline__ float2 unpack2(unsigned long long v) {
    float2 f;
    unsigned lo, hi;
    asm("mov.b64 {%0, %1}, %2;" : "=r"(lo), "=r"(hi) : "l"(v));
    f.x = __uint_as_float(lo); f.y = __uint_as_float(hi);
    return f;
}

// ---------------------------------------------------------------------------
// Kernel 1: both attention MLPs in one launch (grid = 512).
// ---------------------------------------------------------------------------
__global__ __launch_bounds__(256) void att_mlp_kernel(
        const float* __restrict__ x, const float* __restrict__ neibs,
        const float* __restrict__ xw1, const float* __restrict__ xb1,
        const float* __restrict__ xw2, const float* __restrict__ xb2,
        const float* __restrict__ nw1, const float* __restrict__ nb1,
        const float* __restrict__ nw2, const float* __restrict__ nb2) {
    __shared__ float w1s[DIN * H];
    __shared__ float w2s[H * H];
    __shared__ float b1s[H], b2s[H];
    __shared__ float xs[8 * DIN];
    __shared__ float t1s[8 * 33];

    const int tid = threadIdx.x;
    const int which = blockIdx.x >= 256;
    const int row0 = (blockIdx.x & 255) * 8;

    const float* in = which ? neibs : x;
    const float* w1 = which ? nw1 : xw1;
    const float* b1 = which ? nb1 : xb1;
    const float* w2 = which ? nw2 : xw2;
    const float* b2 = which ? nb2 : xb2;

    for (int i = tid; i < DIN * H; i += 256) w1s[i] = w1[i];
    for (int i = tid; i < H * H; i += 256)   w2s[i] = w2[i];
    if (tid < H) { b1s[tid] = b1[tid]; b2s[tid] = b2[tid]; }
    for (int i = tid; i < 8 * DIN; i += 256) xs[i] = in[row0 * DIN + i];
    __syncthreads();

    const int r = tid >> 5;
    const int h = tid & 31;

    float a0 = b1s[h], a1 = 0.f, a2 = 0.f, a3 = 0.f;
    #pragma unroll 8
    for (int k = 0; k < DIN; k += 4) {
        a0 += xs[r * DIN + k + 0] * w1s[(k + 0) * H + h];
        a1 += xs[r * DIN + k + 1] * w1s[(k + 1) * H + h];
        a2 += xs[r * DIN + k + 2] * w1s[(k + 2) * H + h];
        a3 += xs[r * DIN + k + 3] * w1s[(k + 3) * H + h];
    }
    float acc = (a0 + a1) + (a2 + a3);

    t1s[r * 33 + h] = tanhf(acc);
    __syncwarp();

    float c0 = b2s[h], c1 = 0.f, c2 = 0.f, c3 = 0.f;
    #pragma unroll
    for (int kk = 0; kk < H; kk += 4) {
        c0 += t1s[r * 33 + kk + 0] * w2s[(kk + 0) * H + h];
        c1 += t1s[r * 33 + kk + 1] * w2s[(kk + 1) * H + h];
        c2 += t1s[r * 33 + kk + 2] * w2s[(kk + 2) * H + h];
        c3 += t1s[r * 33 + kk + 3] * w2s[(kk + 3) * H + h];
    }
    float acc2 = (c0 + c1) + (c2 + c3);

    float* out = which ? g_natt : g_xatt;
    out[(row0 + r) * H + h] = acc2;
}

// ---------------------------------------------------------------------------
// Kernel 2: split-K flash aggregation. BOTH matmuls via tf32 MMA.
// S: each warp computes a 16x8 sub-tile of the 32x32 score tile
//    (warp = (mhalf, nquarter)); A-frags (x_att) preloaded once per block.
// No online max (scores bounded, exp safe; softmax shift-invariant).
// Grid = 64 row-blocks * 4 splits = 256 blocks, 256 threads (8 warps).
// ---------------------------------------------------------------------------
__global__ __launch_bounds__(256) void flash_part_kernel(
        const float* __restrict__ neibs, const float* __restrict__ mask) {
    __shared__ float xa[BM * 36];       // x_att tile (tf32 bits), block-invariant
    __shared__ float naT[H * NAS];      // transposed neib_att tile (tf32 bits)
    __shared__ float ps[BM * 36];       // exp weights (tf32 bits)
    __shared__ float nb[BN * NBS];      // neighbor features (tf32 bits) 33 KB
    __shared__ float lred[4][BM];       // l reduction across n-quarter warps

    const int tid   = threadIdx.x;
    const int split = blockIdx.x & (NSPLIT - 1);
    const int row0  = (blockIdx.x >> 2) * BM;
    const int jstart = split * CHUNK;

    const int warp = tid >> 5;
    const int lane = tid & 31;
    const int gid  = lane >> 2;         // 0..7
    const int tg   = lane & 3;          // 0..3
    const int n0   = warp * 32;         // PV n-slice

    // S-phase warp mapping: mhalf (rows mh*16..+15), nquarter (cols nq*8..+7)
    const int mh = warp >> 2;           // 0..1
    const int nq = warp & 3;            // 0..3
    const int srowA = mh * 16 + gid;    // fragment row A
    const int srowB = srowA + 8;        // fragment row B
    const int scol  = nq * 8 + 2 * tg;  // fragment col pair base

    // stage xa once (tf32)
    for (int i = tid; i < BM * H; i += 256) {
        int r = i >> 5, hh = i & 31;
        xa[r * 36 + hh] = __uint_as_float(f2t(g_xatt[(size_t)(row0 + r) * H + hh]));
    }
    __syncthreads();

    // preload S A-fragments (x_att rows for this warp's m-half), 16 regs
    unsigned sa[4][4];
    #pragma unroll
    for (int kt = 0; kt < 4; kt++) {
        const int kc = kt * 8 + tg;
        sa[kt][0] = fu(xa[srowA * 36 + kc]);
        sa[kt][1] = fu(xa[srowB * 36 + kc]);
        sa[kt][2] = fu(xa[srowA * 36 + kc + 4]);
        sa[kt][3] = fu(xa[srowB * 36 + kc + 4]);
    }

    float lacc0 = 0.0f, lacc1 = 0.0f;   // l partials for rows srowA, srowB
    float4 acc[2][4];                   // PV accum [m-tile][n-tile]
    #pragma unroll
    for (int mt = 0; mt < 2; mt++)
        #pragma unroll
        for (int nt = 0; nt < 4; nt++)
            acc[mt][nt] = make_float4(0.f, 0.f, 0.f, 0.f);

    for (int t = 0; t < CHUNK / BN; t++) {
        const int jcol0 = jstart + t * BN;

        // prefetch mask in fragment layout (overlaps staging)
        float2 mv0 = *(const float2*)(mask + (size_t)(row0 + srowA) * NN + jcol0 + scol);
        float2 mv1 = *(const float2*)(mask + (size_t)(row0 + srowB) * NN + jcol0 + scol);

        // stage neib_att tile transposed (tf32), stride NAS
        for (int i = tid; i < BN * H; i += 256) {
            int j = i & 31, hh = i >> 5;
            naT[hh * NAS + j] =
                __uint_as_float(f2t(g_natt[(size_t)(jcol0 + j) * H + hh]));
        }
        // stage neighbor features (tf32), stride NBS
        #pragma unroll
        for (int i = tid; i < BN * DIN / 4; i += 256) {
            int j = i >> 6, c4 = (i & 63) * 4;
            float4 v = *(const float4*)(neibs + (size_t)(jcol0 + j) * DIN + c4);
            float* dst = nb + j * NBS + c4;
            dst[0] = __uint_as_float(f2t(v.x));
            dst[1] = __uint_as_float(f2t(v.y));
            dst[2] = __uint_as_float(f2t(v.z));
            dst[3] = __uint_as_float(f2t(v.w));
        }
        __syncthreads();

        // ---- S = x_att @ naT^T via MMA (K=32 in 4 k-steps) ----
        float4 sfrag = make_float4(0.f, 0.f, 0.f, 0.f);
        #pragma unroll
        for (int kt = 0; kt < 4; kt++) {
            // B frags: banks 8t+g, conflict-free at stride NAS=40
            unsigned b0 = fu(naT[(kt * 8 + tg) * NAS + nq * 8 + gid]);
            unsigned b1 = fu(naT[(kt * 8 + tg + 4) * NAS + nq * 8 + gid]);
            mma8(sfrag, sa[kt][0], sa[kt][1], sa[kt][2], sa[kt][3], b0, b1);
        }

        // mask -> exp -> p (exp(0)=1 on masked entries matches reference)
        float p00 = __expf(sfrag.x * mv0.x);
        float p01 = __expf(sfrag.y * mv0.y);
        float p10 = __expf(sfrag.z * mv1.x);
        float p11 = __expf(sfrag.w * mv1.y);
        lacc0 += p00 + p01;
        lacc1 += p10 + p11;

        *(float2*)(ps + srowA * 36 + scol) = make_float2(
            __uint_as_float(f2t(p00)), __uint_as_float(f2t(p01)));
        *(float2*)(ps + srowB * 36 + scol) = make_float2(
            __uint_as_float(f2t(p10)), __uint_as_float(f2t(p11)));

        __syncthreads();   // ps visible to all warps (PV A-frags span 32 rows)

        // ---- PV: tf32 mma, K = 32 in 4 steps (conflict-free scalar frags) --
        #pragma unroll
        for (int kt = 0; kt < 4; kt++) {
            const int kc = kt * 8 + tg;
            unsigned a0m0 = fu(ps[gid * 36 + kc]);
            unsigned a1m0 = fu(ps[(gid + 8) * 36 + kc]);
            unsigned a2m0 = fu(ps[gid * 36 + kc + 4]);
            unsigned a3m0 = fu(ps[(gid + 8) * 36 + kc + 4]);
            unsigned a0m1 = fu(ps[(gid + 16) * 36 + kc]);
            unsigned a1m1 = fu(ps[(gid + 24) * 36 + kc]);
            unsigned a2m1 = fu(ps[(gid + 16) * 36 + kc + 4]);
            unsigned a3m1 = fu(ps[(gid + 24) * 36 + kc + 4]);
            #pragma unroll
            for (int nt = 0; nt < 4; nt++) {
                const int nc = n0 + nt * 8 + gid;
                unsigned b0 = fu(nb[(kt * 8 + tg) * NBS + nc]);
                unsigned b1 = fu(nb[(kt * 8 + tg + 4) * NBS + nc]);
                mma8(acc[0][nt], a0m0, a1m0, a2m0, a3m0, b0, b1);
                mma8(acc[1][nt], a0m1, a1m1, a2m1, a3m1, b0, b1);
            }
        }
        __syncthreads();
    }

    // ---- l reduction: over tg lanes, then across the 4 n-quarter warps ----
    lacc0 += __shfl_xor_sync(0xffffffffu, lacc0, 1);
    lacc0 += __shfl_xor_sync(0xffffffffu, lacc0, 2);
    lacc1 += __shfl_xor_sync(0xffffffffu, lacc1, 1);
    lacc1 += __shfl_xor_sync(0xffffffffu, lacc1, 2);
    if (tg == 0) {
        lred[nq][srowA] = lacc0;
        lred[nq][srowB] = lacc1;
    }
    __syncthreads();
    if (tid < BM) {
        float L = lred[0][tid] + lred[1][tid] + lred[2][tid] + lred[3][tid];
        g_pl[split * NROWS + row0 + tid] = L;
    }

    // partial outputs (fragment layout -> g_pacc)
    #pragma unroll
    for (int mt = 0; mt < 2; mt++) {
        const int r1 = gid + mt * 16;
        const int r2 = gid + 8 + mt * 16;
        const size_t b1 = ((size_t)split * NROWS + row0 + r1) * DIN;
        const size_t b2 = ((size_t)split * NROWS + row0 + r2) * DIN;
        #pragma unroll
        for (int nt = 0; nt < 4; nt++) {
            const int c = n0 + nt * 8 + 2 * tg;
            *(float2*)(g_pacc + b1 + c) = make_float2(acc[mt][nt].x, acc[mt][nt].y);
            *(float2*)(g_pacc + b2 + c) = make_float2(acc[mt][nt].z, acc[mt][nt].w);
        }
    }
}

// ---------------------------------------------------------------------------
// Kernel 3: combine split partials -> agg = sigmoid((Σ pacc) / (Σ l))
// Full-occupancy: 512 blocks x 256 threads, one float4 per thread.
// ---------------------------------------------------------------------------
__global__ __launch_bounds__(256) void combine_kernel() {
    const int idx4 = blockIdx.x * 256 + threadIdx.x;   // 0 .. NROWS*DIN/4-1
    const int row  = idx4 >> 6;                        // DIN/4 = 64 chunks/row
    const int off  = idx4 * 4;

    float L = 0.0f;
    #pragma unroll
    for (int s = 0; s < NSPLIT; s++)
        L += g_pl[s * NROWS + row];
    const float invL = 1.0f / L;

    float4 a = *(const float4*)(g_pacc + off);
    #pragma unroll
    for (int s = 1; s < NSPLIT; s++) {
        float4 v = *(const float4*)(g_pacc + (size_t)s * NROWS * DIN + off);
        a.x += v.x; a.y += v.y; a.z += v.z; a.w += v.w;
    }
    float4 o;
    o.x = 1.0f / (1.0f + __expf(-a.x * invL));
    o.y = 1.0f / (1.0f + __expf(-a.y * invL));
    o.z = 1.0f / (1.0f + __expf(-a.z * invL));
    o.w = 1.0f / (1.0f + __expf(-a.w * invL));
    *(float4*)(g_agg + off) = o;
}

// ---------------------------------------------------------------------------
// Kernel 4a: fc partial GEMM, f32x2, K split in 8 (64 each).
// Grid = 64 rowblocks * 4 colblocks * 8 ksplit = 2048 blocks, 128 threads.
// ---------------------------------------------------------------------------
__global__ __launch_bounds__(128) void fc_part_kernel(
        const float* __restrict__ x, const float* __restrict__ fcw) {
    __shared__ float AtT[32 * 36];     // [k][row], padded
    __shared__ float Wt[32 * 64];

    const int b    = blockIdx.x;
    const int ks   = b & 7;
    const int col0 = ((b >> 3) & 3) * 64;
    const int row0 = (b >> 5) * 32;

    const float* A = (ks < 4) ? x : g_agg;                // [2048, 256]
    const int acol0 = (ks & 3) * 64;                      // A column base
    const float* W = fcw + (size_t)ks * 64 * DOUT;        // 64 K-rows

    const int tid = threadIdx.x;
    const int rg  = tid >> 4;          // 0..7 -> rows rg*4..+3
    const int cq  = tid & 15;          // 0..15 -> cols cq*4..+3

    unsigned long long acc[4][2];
    #pragma unroll
    for (int i = 0; i < 4; i++) { acc[i][0] = 0ULL; acc[i][1] = 0ULL; }

    #pragma unroll
    for (int kt = 0; kt < 2; kt++) {
        const int kbase = kt * 32;
        // stage A transposed
        for (int i = tid; i < 32 * 32; i += 128) {
            int r = i >> 5, kk = i & 31;
            AtT[kk * 36 + r] = A[(size_t)(row0 + r) * DIN + acol0 + kbase + kk];
        }
        // stage W tile
        #pragma unroll
        for (int i = tid; i < 32 * 64 / 4; i += 128) {
            int kk = i >> 4, cc = (i & 15) * 4;
            *(float4*)(Wt + kk * 64 + cc) =
                *(const float4*)(W + (size_t)(kbase + kk) * DOUT + col0 + cc);
        }
        __syncthreads();

        #pragma unroll 8
        for (int k = 0; k < 32; k++) {
            float4 av = *(const float4*)(AtT + k * 36 + rg * 4);
            ulonglong2 wv = *(const ulonglong2*)(Wt + k * 64 + cq * 4);
            unsigned long long a0 = bcast2(av.x);
            unsigned long long a1 = bcast2(av.y);
            unsigned long long a2 = bcast2(av.z);
            unsigned long long a3 = bcast2(av.w);
            fma2(acc[0][0], a0, wv.x); fma2(acc[0][1], a0, wv.y);
            fma2(acc[1][0], a1, wv.x); fma2(acc[1][1], a1, wv.y);
            fma2(acc[2][0], a2, wv.x); fma2(acc[2][1], a2, wv.y);
            fma2(acc[3][0], a3, wv.x); fma2(acc[3][1], a3, wv.y);
        }
        __syncthreads();
    }

    #pragma unroll
    for (int i = 0; i < 4; i++) {
        float2 lo = unpack2(acc[i][0]);
        float2 hi = unpack2(acc[i][1]);
        *(float4*)(g_fcp + ((size_t)ks * NROWS + row0 + rg * 4 + i) * DOUT
                   + col0 + cq * 4) = make_float4(lo.x, lo.y, hi.x, hi.y);
    }
}

// ---------------------------------------------------------------------------
// Kernel 4b: out = sigmoid(sum of 8 partials + b)
// ---------------------------------------------------------------------------
__global__ __launch_bounds__(256) void fc_epilogue_kernel(
        const float* __restrict__ fcb, float* __restrict__ out) {
    const int idx4 = blockIdx.x * 256 + threadIdx.x;
    const int off  = idx4 * 4;
    const int col  = off & (DOUT - 1);

    float4 a = *(const float4*)(g_fcp + off);
    #pragma unroll
    for (int s = 1; s < FCKS; s++) {
        float4 p = *(const float4*)(g_fcp + (size_t)s * NROWS * DOUT + off);
        a.x += p.x; a.y += p.y; a.z += p.z; a.w += p.w;
    }
    float4 b4 = *(const float4*)(fcb + col);
    float4 o;
    o.x = 1.0f / (1.0f + __expf(-(a.x + b4.x)));
    o.y = 1.0f / (1.0f + __expf(-(a.y + b4.y)));
    o.z = 1.0f / (1.0f + __expf(-(a.z + b4.z)));
    o.w = 1.0f / (1.0f + __expf(-(a.w + b4.w)));
    *(float4*)(out + off) = o;
}

// ---------------------------------------------------------------------------
extern "C" void kernel_launch(void* const* d_in, const int* in_sizes, int n_in,
                              void* d_out, int out_size) {
    (void)in_sizes; (void)n_in; (void)out_size;
    const float* x      = (const float*)d_in[0];
    const float* neibs  = (const float*)d_in[1];
    // d_in[2] = edge_emb: dead code in the reference, intentionally untouched
    const float* mask   = (const float*)d_in[3];
    const float* ax_w1  = (const float*)d_in[4];
    const float* ax_b1  = (const float*)d_in[5];
    const float* ax_w2  = (const float*)d_in[6];
    const float* ax_b2  = (const float*)d_in[7];
    const float* an_w1  = (const float*)d_in[8];
    const float* an_b1  = (const float*)d_in[9];
    const float* an_w2  = (const float*)d_in[10];
    const float* an_b2  = (const float*)d_in[11];
    // d_in[12..15] = ae_* : dead code
    const float* fcx_w  = (const float*)d_in[16];
    const float* fcx_b  = (const float*)d_in[17];
    float* out = (float*)d_out;

    att_mlp_kernel<<<512, 256>>>(x, neibs, ax_w1, ax_b1, ax_w2, ax_b2,
                                 an_w1, an_b1, an_w2, an_b2);
    flash_part_kernel<<<(NROWS / BM) * NSPLIT, 256>>>(neibs, mask);
    combine_kernel<<<NROWS * DIN / 1024, 256>>>();
    fc_part_kernel<<<(NROWS / 32) * (DOUT / 64) * FCKS, 128>>>(x, fcx_w);
    fc_epilogue_kernel<<<NROWS * DOUT / 1024, 256>>>(fcx_b, out);
}